// round 4
// baseline (speedup 1.0000x reference)
#include <cuda_runtime.h>
#include <math.h>

#define BB 4
#define NN 1024
#define CC 512
#define HH 32
#define WW 32
#define NH 8
#define HD 64

// ---------------- scratch (static __device__, allocation-free) ----------------
__device__ float g_xt [BB*CC*NN];          // x transposed [B][C][N]
__device__ float g_q  [BB*CC*NN];          // Q [B][C][N]
__device__ float g_k  [BB*CC*NN];          // K [B][C][N]
__device__ float g_v  [BB*CC*NN];          // V [B][C][N]
__device__ float g_h  [BB*CC*NN];          // dwconv+gelu [B][C][N]
__device__ float g_off[BB*16*NN];          // offsets raw (tanh*2) [B][16][N]
__device__ float g_sxy[BB*NH*NN*2];        // pixel-space sample coords
__device__ float g_ksmp[BB*NH*HD*NN];      // sampled K [bh][d][n]
__device__ float g_vsmp[BB*NH*HD*NN];      // sampled V [bh][d][n]
__device__ float g_b0 [64*64];
__device__ float g_M  [NN*64];
__device__ float g_Mt [64*NN];
__device__ float g_tmpMB[NN*64];
__device__ float g_bias[NN*NN];            // 4 MB
__device__ float g_sc [32u*1024u*1024u];   // scores/probs, 128 MB
__device__ float g_att[BB*NN*CC];          // attention out [B][N][C]
__device__ float g_oo [BB*CC*NN];          // o-proj out [B][C][N]

// ---------------- transpose [R][C] -> [C][R], batched ----------------
__global__ void k_transpose(const float* __restrict__ in, float* __restrict__ out,
                            int R, int Ccols) {
    __shared__ float tile[32][33];
    int b = blockIdx.z;
    const float* ip = in + (size_t)b * R * Ccols;
    float* op = out + (size_t)b * R * Ccols;
    int c0 = blockIdx.x * 32, r0 = blockIdx.y * 32;
    #pragma unroll
    for (int i = threadIdx.y; i < 32; i += 8)
        tile[i][threadIdx.x] = ip[(size_t)(r0 + i) * Ccols + c0 + threadIdx.x];
    __syncthreads();
    #pragma unroll
    for (int i = threadIdx.y; i < 32; i += 8)
        op[(size_t)(c0 + i) * R + r0 + threadIdx.x] = tile[threadIdx.x][i];
}

// ---------------- GEMM: out[b][m][n] = sum_k A[m][k]*Bm[b][n][k] + bias[m] ----
// A: [M][K] row-major (k contiguous), Bm: [B][Nd][K] (k contiguous)
__global__ void k_gemm_wx(const float* __restrict__ A, const float* __restrict__ Bm,
                          const float* __restrict__ bias, float* __restrict__ out,
                          int M, int Nd, int K) {
    __shared__ float As[16][65];
    __shared__ float Bs[16][65];
    int tid = threadIdx.x;
    int tx = tid & 15, ty = tid >> 4;
    int m0 = blockIdx.y * 64, n0 = blockIdx.x * 64;
    const float* Ap = A + (size_t)m0 * K;
    const float* Bp = Bm + (size_t)blockIdx.z * Nd * K + (size_t)n0 * K;
    int lr = tid >> 2, lk = (tid & 3) * 4;
    float acc[4][4];
    #pragma unroll
    for (int i = 0; i < 4; i++)
        #pragma unroll
        for (int j = 0; j < 4; j++) acc[i][j] = 0.f;
    for (int k0 = 0; k0 < K; k0 += 16) {
        float4 a4 = *(const float4*)(Ap + (size_t)lr * K + k0 + lk);
        float4 b4 = *(const float4*)(Bp + (size_t)lr * K + k0 + lk);
        As[lk + 0][lr] = a4.x; As[lk + 1][lr] = a4.y; As[lk + 2][lr] = a4.z; As[lk + 3][lr] = a4.w;
        Bs[lk + 0][lr] = b4.x; Bs[lk + 1][lr] = b4.y; Bs[lk + 2][lr] = b4.z; Bs[lk + 3][lr] = b4.w;
        __syncthreads();
        #pragma unroll
        for (int k = 0; k < 16; k++) {
            float ra[4], rb[4];
            #pragma unroll
            for (int i = 0; i < 4; i++) ra[i] = As[k][ty * 4 + i];
            #pragma unroll
            for (int j = 0; j < 4; j++) rb[j] = Bs[k][tx * 4 + j];
            #pragma unroll
            for (int i = 0; i < 4; i++)
                #pragma unroll
                for (int j = 0; j < 4; j++) acc[i][j] += ra[i] * rb[j];
        }
        __syncthreads();
    }
    #pragma unroll
    for (int i = 0; i < 4; i++) {
        int m = m0 + ty * 4 + i;
        float bv = bias[m];
        #pragma unroll
        for (int j = 0; j < 4; j++)
            out[((size_t)blockIdx.z * M + m) * Nd + n0 + tx * 4 + j] = acc[i][j] + bv;
    }
}

// ---------------- depthwise 5x5 conv + exact GELU ----------------
__global__ void k_dwconv(const float* __restrict__ xt, const float* __restrict__ w,
                         const float* __restrict__ b, float* __restrict__ out) {
    int n = blockIdx.x * 256 + threadIdx.x;
    int c = blockIdx.y, bb = blockIdx.z;
    int y = n >> 5, x = n & 31;
    const float* p = xt + ((size_t)bb * CC + c) * NN;
    const float* wf = w + c * 25;
    float acc = b[c];
    #pragma unroll
    for (int dy = 0; dy < 5; dy++) {
        int yy = y + dy - 2;
        if (yy < 0 || yy >= HH) continue;
        #pragma unroll
        for (int dx = 0; dx < 5; dx++) {
            int xx = x + dx - 2;
            if (xx < 0 || xx >= WW) continue;
            acc += p[yy * WW + xx] * wf[dy * 5 + dx];
        }
    }
    out[((size_t)bb * CC + c) * NN + n] = 0.5f * acc * (1.0f + erff(acc * 0.7071067811865476f));
}

// ---------------- offset head: 1x1 conv (16 out ch), tanh * 2 ----------------
__global__ void k_offproj(const float* __restrict__ h, const float* __restrict__ ow,
                          float* __restrict__ off) {
    int n = blockIdx.x * 256 + threadIdx.x;
    int oc = blockIdx.y, bb = blockIdx.z;
    const float* hp = h + (size_t)bb * CC * NN + n;
    const float* wp = ow + oc * CC;
    float acc = 0.f;
    for (int c = 0; c < CC; c++) acc += hp[(size_t)c * NN] * wp[c];
    off[((size_t)bb * 16 + oc) * NN + n] = tanhf(acc) * 2.0f;
}

// ---------------- sample coords (grid + offset, clip, -> pixel space) --------
__global__ void k_samp(const float* __restrict__ off, float* __restrict__ sxy) {
    int n = blockIdx.x * 256 + threadIdx.x;
    int hh = blockIdx.y, bb = blockIdx.z;
    float ox = off[((size_t)bb * 16 + hh * 2    ) * NN + n];
    float oy = off[((size_t)bb * 16 + hh * 2 + 1) * NN + n];
    int y = n >> 5, x = n & 31;
    float gx = -1.0f + 2.0f * x / 31.0f;
    float gy = -1.0f + 2.0f * y / 31.0f;
    float sx = fminf(fmaxf(gx + ox, -1.f), 1.f);
    float sy = fminf(fmaxf(gy + oy, -1.f), 1.f);
    size_t o = (((size_t)bb * NH + hh) * NN + n) * 2;
    sxy[o]     = (sx + 1.0f) * 16.0f - 0.5f;   // (s+1)*Wi/2 - 0.5
    sxy[o + 1] = (sy + 1.0f) * 16.0f - 0.5f;
}

// ---------------- bilinear grid sample (zeros padding) for K and V -----------
__global__ void k_gsample(const float* __restrict__ sxy, const float* __restrict__ Kg,
                          const float* __restrict__ Vg, float* __restrict__ Ks,
                          float* __restrict__ Vs) {
    int n = blockIdx.x * 256 + threadIdx.x;
    int d = blockIdx.y, bh = blockIdx.z;
    int bb = bh >> 3, hh = bh & 7;
    size_t so = ((size_t)bh * NN + n) * 2;
    float px = sxy[so], py = sxy[so + 1];
    float x0f = floorf(px), y0f = floorf(py);
    int x0 = (int)x0f, y0 = (int)y0f;
    float fx = px - x0f, fy = py - y0f;
    const float* kp = Kg + ((size_t)bb * CC + hh * HD + d) * NN;
    const float* vp = Vg + ((size_t)bb * CC + hh * HD + d) * NN;
    float ks = 0.f, vs = 0.f;
    #pragma unroll
    for (int dy = 0; dy < 2; dy++) {
        int yi = y0 + dy;
        if (yi < 0 || yi >= HH) continue;
        float wy = dy ? fy : 1.0f - fy;
        #pragma unroll
        for (int dx = 0; dx < 2; dx++) {
            int xi = x0 + dx;
            if (xi < 0 || xi >= WW) continue;
            float wt = wy * (dx ? fx : 1.0f - fx);
            int f = yi * WW + xi;
            ks += kp[f] * wt;
            vs += vp[f] * wt;
        }
    }
    size_t oo = ((size_t)bh * HD + d) * NN + n;
    Ks[oo] = ks;
    Vs[oo] = vs;
}

// ---------------- relative position bias table lookup (wsz=8) ----------------
__global__ void k_bias0(const float* __restrict__ table, float* __restrict__ b0) {
    int t = blockIdx.x * 256 + threadIdx.x;
    if (t >= 4096) return;
    int i = t >> 6, j = t & 63;
    int iy = i >> 3, ix = i & 7, jy = j >> 3, jx = j & 7;
    int idx = (iy - jy + 7) * 15 + (ix - jx + 7);
    b0[t] = table[idx];
}

// ---------------- bicubic resize matrix M [1024][64] and Mt ------------------
__global__ void k_bicubicM(float* __restrict__ M, float* __restrict__ Mt) {
    int r = blockIdx.x * 256 + threadIdx.x;
    if (r >= NN) return;
    for (int c = 0; c < 64; c++) { M[r * 64 + c] = 0.f; Mt[c * NN + r] = 0.f; }
    const float a = -0.75f;
    float src = (r + 0.5f) * (64.0f / 1024.0f) - 0.5f;
    float i0f = floorf(src);
    float t = src - i0f;
    int i0 = (int)i0f;
    #pragma unroll
    for (int k = -1; k <= 2; k++) {
        int idx = min(max(i0 + k, 0), 63);
        float d = fabsf(t - (float)k);
        float w;
        if (d <= 1.0f)      w = (a + 2.0f) * d * d * d - (a + 3.0f) * d * d + 1.0f;
        else if (d < 2.0f)  w = a * d * d * d - 5.0f * a * d * d + 8.0f * a * d - 4.0f * a;
        else                w = 0.0f;
        M[r * 64 + idx]  += w;
        Mt[idx * NN + r] += w;
    }
}

// tmp = M @ bias0  [1024][64]
__global__ void k_Mb0(const float* __restrict__ M, const float* __restrict__ b0,
                      float* __restrict__ tmp) {
    int t = blockIdx.x * 256 + threadIdx.x;    // 65536
    int r = t >> 6, j = t & 63;
    float acc = 0.f;
    for (int c = 0; c < 64; c++) acc += M[r * 64 + c] * b0[c * 64 + j];
    tmp[t] = acc;
}

// bias[i][j] = sum_e tmp[i][e] * Mt[e][j]
__global__ void k_biasfull(const float* __restrict__ tmp, const float* __restrict__ Mt,
                           float* __restrict__ bias) {
    int t = blockIdx.x * 256 + threadIdx.x;    // 1M
    int i = t >> 10, j = t & 1023;
    float acc = 0.f;
    for (int e = 0; e < 64; e++) acc += tmp[i * 64 + e] * Mt[e * NN + j];
    bias[t] = acc;
}

// ---------------- scores: S[bh][i][j] = 0.125 * Q^T K + bias -----------------
__global__ void k_scores(const float* __restrict__ Qg, const float* __restrict__ Kg,
                         const float* __restrict__ biasf, float* __restrict__ Sg) {
    __shared__ __align__(16) float As[16][64];
    __shared__ __align__(16) float Bs[16][64];
    int bh = blockIdx.z;
    int bb = bh >> 3, hh = bh & 7;
    const float* Qp = Qg + ((size_t)bb * CC + hh * HD) * NN;   // [64 d][1024 i]
    const float* Kp = Kg + ((size_t)bh) * HD * NN;             // sampled K [64 d][1024 j]
    int i0 = blockIdx.y * 64, j0 = blockIdx.x * 64;
    int tid = threadIdx.x, tx = tid & 15, ty = tid >> 4;
    int lk = tid >> 4, li4 = (tid & 15) * 4;
    float acc[4][4];
    #pragma unroll
    for (int i = 0; i < 4; i++)
        #pragma unroll
        for (int j = 0; j < 4; j++) acc[i][j] = 0.f;
    for (int d0 = 0; d0 < 64; d0 += 16) {
        *(float4*)&As[lk][li4] = *(const float4*)(Qp + (size_t)(d0 + lk) * NN + i0 + li4);
        *(float4*)&Bs[lk][li4] = *(const float4*)(Kp + (size_t)(d0 + lk) * NN + j0 + li4);
        __syncthreads();
        #pragma unroll
        for (int k = 0; k < 16; k++) {
            float ra[4], rb[4];
            #pragma unroll
            for (int i = 0; i < 4; i++) ra[i] = As[k][ty * 4 + i];
            #pragma unroll
            for (int j = 0; j < 4; j++) rb[j] = Bs[k][tx * 4 + j];
            #pragma unroll
            for (int i = 0; i < 4; i++)
                #pragma unroll
                for (int j = 0; j < 4; j++) acc[i][j] += ra[i] * rb[j];
        }
        __syncthreads();
    }
    #pragma unroll
    for (int i = 0; i < 4; i++) {
        int ii = i0 + ty * 4 + i;
        #pragma unroll
        for (int j = 0; j < 4; j++) {
            int jj = j0 + tx * 4 + j;
            Sg[((size_t)bh << 20) + (size_t)ii * NN + jj] =
                acc[i][j] * 0.125f + biasf[(size_t)ii * NN + jj];
        }
    }
}

// ---------------- softmax over rows of 1024 (in place) -----------------------
__global__ void k_softmax(float* __restrict__ S) {
    float* p = S + (size_t)blockIdx.x * NN;
    int t = threadIdx.x;
    float v0 = p[t], v1 = p[t + 256], v2 = p[t + 512], v3 = p[t + 768];
    float m = fmaxf(fmaxf(v0, v1), fmaxf(v2, v3));
    __shared__ float rmax[8], rsum[8], bc[2];
    #pragma unroll
    for (int o = 16; o > 0; o >>= 1) m = fmaxf(m, __shfl_xor_sync(0xffffffffu, m, o));
    if ((t & 31) == 0) rmax[t >> 5] = m;
    __syncthreads();
    if (t == 0) {
        float mm = rmax[0];
        #pragma unroll
        for (int i = 1; i < 8; i++) mm = fmaxf(mm, rmax[i]);
        bc[0] = mm;
    }
    __syncthreads();
    m = bc[0];
    v0 = expf(v0 - m); v1 = expf(v1 - m); v2 = expf(v2 - m); v3 = expf(v3 - m);
    float s = v0 + v1 + v2 + v3;
    #pragma unroll
    for (int o = 16; o > 0; o >>= 1) s += __shfl_xor_sync(0xffffffffu, s, o);
    if ((t & 31) == 0) rsum[t >> 5] = s;
    __syncthreads();
    if (t == 0) {
        float ss = 0.f;
        #pragma unroll
        for (int i = 0; i < 8; i++) ss += rsum[i];
        bc[1] = ss;
    }
    __syncthreads();
    float inv = 1.0f / bc[1];
    p[t] = v0 * inv; p[t + 256] = v1 * inv; p[t + 512] = v2 * inv; p[t + 768] = v3 * inv;
}

// ---------------- out = P @ V^T, written as [B][N][C] ------------------------
__global__ void k_attout(const float* __restrict__ Pg, const float* __restrict__ Vsg,
                         float* __restrict__ att) {
    __shared__ float As[16][65];
    __shared__ float Bs[16][65];
    int bh = blockIdx.z;
    int bb = bh >> 3, hh = bh & 7;
    const float* Pp = Pg + ((size_t)bh << 20);            // [1024 i][1024 j]
    const float* Vp = Vsg + (size_t)bh * HD * NN;         // [64 d][1024 j]
    int i0 = blockIdx.y * 64;                             // d tile = all 64
    int tid = threadIdx.x, tx = tid & 15, ty = tid >> 4;
    int lr = tid >> 2, lk = (tid & 3) * 4;
    float acc[4][4];
    #pragma unroll
    for (int i = 0; i < 4; i++)
        #pragma unroll
        for (int j = 0; j < 4; j++) acc[i][j] = 0.f;
    for (int k0 = 0; k0 < NN; k0 += 16) {
        float4 a4 = *(const float4*)(Pp + (size_t)(i0 + lr) * NN + k0 + lk);
        float4 b4 = *(const float4*)(Vp + (size_t)lr * NN + k0 + lk);
        As[lk + 0][lr] = a4.x; As[lk + 1][lr] = a4.y; As[lk + 2][lr] = a4.z; As[lk + 3][lr] = a4.w;
        Bs[lk + 0][lr] = b4.x; Bs[lk + 1][lr] = b4.y; Bs[lk + 2][lr] = b4.z; Bs[lk + 3][lr] = b4.w;
        __syncthreads();
        #pragma unroll
        for (int k = 0; k < 16; k++) {
            float ra[4], rb[4];
            #pragma unroll
            for (int i = 0; i < 4; i++) ra[i] = As[k][ty * 4 + i];
            #pragma unroll
            for (int j = 0; j < 4; j++) rb[j] = Bs[k][tx * 4 + j];
            #pragma unroll
            for (int i = 0; i < 4; i++)
                #pragma unroll
                for (int j = 0; j < 4; j++) acc[i][j] += ra[i] * rb[j];
        }
        __syncthreads();
    }
    #pragma unroll
    for (int i = 0; i < 4; i++) {
        int ii = i0 + ty * 4 + i;
        #pragma unroll
        for (int j = 0; j < 4; j++)
            att[((size_t)bb * NN + ii) * CC + hh * HD + tx * 4 + j] = acc[i][j];
    }
}

// ---------------- launch ----------------
extern "C" void kernel_launch(void* const* d_in, const int* in_sizes, int n_in,
                              void* d_out, int out_size) {
    const float* x     = (const float*)d_in[0];
    const float* q_w   = (const float*)d_in[1];
    const float* q_b   = (const float*)d_in[2];
    const float* k_w   = (const float*)d_in[3];
    const float* k_b   = (const float*)d_in[4];
    const float* v_w   = (const float*)d_in[5];
    const float* v_b   = (const float*)d_in[6];
    const float* o_w   = (const float*)d_in[7];
    const float* o_b   = (const float*)d_in[8];
    const float* dw_w  = (const float*)d_in[9];
    const float* dw_b  = (const float*)d_in[10];
    const float* off_w = (const float*)d_in[11];
    const float* table = (const float*)d_in[12];

    float *p_xt, *p_q, *p_k, *p_v, *p_h, *p_off, *p_sxy, *p_ks, *p_vs;
    float *p_b0, *p_M, *p_Mt, *p_tmp, *p_bias, *p_sc, *p_att, *p_oo;
    cudaGetSymbolAddress((void**)&p_xt,  g_xt);
    cudaGetSymbolAddress((void**)&p_q,   g_q);
    cudaGetSymbolAddress((void**)&p_k,   g_k);
    cudaGetSymbolAddress((void**)&p_v,   g_v);
    cudaGetSymbolAddress((void**)&p_h,   g_h);
    cudaGetSymbolAddress((void**)&p_off, g_off);
    cudaGetSymbolAddress((void**)&p_sxy, g_sxy);
    cudaGetSymbolAddress((void**)&p_ks,  g_ksmp);
    cudaGetSymbolAddress((void**)&p_vs,  g_vsmp);
    cudaGetSymbolAddress((void**)&p_b0,  g_b0);
    cudaGetSymbolAddress((void**)&p_M,   g_M);
    cudaGetSymbolAddress((void**)&p_Mt,  g_Mt);
    cudaGetSymbolAddress((void**)&p_tmp, g_tmpMB);
    cudaGetSymbolAddress((void**)&p_bias,g_bias);
    cudaGetSymbolAddress((void**)&p_sc,  g_sc);
    cudaGetSymbolAddress((void**)&p_att, g_att);
    cudaGetSymbolAddress((void**)&p_oo,  g_oo);

    // x [B][N][C] -> xt [B][C][N] (for spatially-coalesced dwconv reads)
    k_transpose<<<dim3(CC / 32, NN / 32, BB), dim3(32, 8)>>>(x, p_xt, NN, CC);

    // Q/K/V projections (x itself is k-contiguous [B][N][C])
    k_gemm_wx<<<dim3(16, 8, BB), 256>>>(q_w, x, q_b, p_q, CC, NN, CC);
    k_gemm_wx<<<dim3(16, 8, BB), 256>>>(k_w, x, k_b, p_k, CC, NN, CC);
    k_gemm_wx<<<dim3(16, 8, BB), 256>>>(v_w, x, v_b, p_v, CC, NN, CC);

    // offset network
    k_dwconv <<<dim3(4, CC, BB), 256>>>(p_xt, dw_w, dw_b, p_h);
    k_offproj<<<dim3(4, 16, BB), 256>>>(p_h, off_w, p_off);
    k_samp   <<<dim3(4, NH, BB), 256>>>(p_off, p_sxy);

    // deformable sampling of K and V
    k_gsample<<<dim3(4, HD, BB * NH), 256>>>(p_sxy, p_k, p_v, p_ks, p_vs);

    // relative-position bias: table -> 64x64 -> bicubic resize to 1024x1024
    k_bias0   <<<16, 256>>>(table, p_b0);
    k_bicubicM<<<4, 256>>>(p_M, p_Mt);
    k_Mb0     <<<256, 256>>>(p_M, p_b0, p_tmp);
    k_biasfull<<<4096, 256>>>(p_tmp, p_Mt, p_bias);

    // attention
    k_scores <<<dim3(16, 16, BB * NH), 256>>>(p_q, p_ks, p_bias, p_sc);
    k_softmax<<<BB * NH * NN, 256>>>(p_sc);
    k_attout <<<dim3(1, 16, BB * NH), 256>>>(p_sc, p_vs, p_att);

    // output projection + final transpose to [B][N][C]
    k_gemm_wx  <<<dim3(16, 8, BB), 256>>>(o_w, p_att, o_b, p_oo, CC, NN, CC);
    k_transpose<<<dim3(NN / 32, CC / 32, BB), dim3(32, 8)>>>(p_oo, (float*)d_out, CC, NN);
}

// round 13
// speedup vs baseline: 1.2156x; 1.2156x over previous
#include <cuda_runtime.h>
#include <math.h>

#define BB 4
#define NN 1024
#define CC 512
#define HH 32
#define WW 32
#define NH 8
#define HD 64

// ---------------- scratch (static __device__, allocation-free) ----------------
__device__ float g_xt [BB*CC*NN];          // x transposed [B][C][N]
__device__ float g_q  [BB*CC*NN];          // Q [B][C][N]
__device__ float g_k  [BB*CC*NN];          // K [B][C][N]
__device__ float g_v  [BB*CC*NN];          // V [B][C][N]
__device__ float g_h  [BB*CC*NN];          // dwconv+gelu [B][C][N]
__device__ float g_off[BB*16*NN];          // offsets raw (tanh*2) [B][16][N]
__device__ float g_sxy[BB*NH*NN*2];        // pixel-space sample coords
__device__ float g_ksmp[BB*NH*HD*NN];      // sampled K [bh][d][n]
__device__ float g_vsmp[BB*NH*HD*NN];      // sampled V [bh][d][n]
__device__ float g_b0 [64*64];
__device__ float g_M  [NN*64];
__device__ float g_Mt [64*NN];
__device__ float g_tmpMB[NN*64];
__device__ float g_bias[NN*NN];            // 4 MB
__device__ float g_sc [32u*1024u*1024u];   // scores/probs, 128 MB
__device__ float g_att[BB*NN*CC];          // attention out [B][N][C]
__device__ float g_oo [BB*CC*NN];          // o-proj out [B][C][N]

// ---------------- packed f32x2 helpers ----------------
__device__ __forceinline__ unsigned long long f2pack(float lo, float hi) {
    unsigned long long r;
    asm("mov.b64 %0, {%1, %2};" : "=l"(r) : "f"(lo), "f"(hi));
    return r;
}
__device__ __forceinline__ void f2unpack(unsigned long long v, float& lo, float& hi) {
    asm("mov.b64 {%0, %1}, %2;" : "=f"(lo), "=f"(hi) : "l"(v));
}
__device__ __forceinline__ void ffma2(unsigned long long& d, unsigned long long a,
                                      unsigned long long b) {
    asm("fma.rn.f32x2 %0, %1, %2, %0;" : "+l"(d) : "l"(a), "l"(b));
}

// 8x8 microtile inner product step on smem rows As[k][m], Bs[k][n]
#define MICRO_8X8_STEP(As, Bs, mbase, nbase)                                     \
    {                                                                            \
        float4 a0 = *(const float4*)&As[k][(mbase)];                             \
        float4 a1 = *(const float4*)&As[k][(mbase) + 4];                         \
        float4 b0 = *(const float4*)&Bs[k][(nbase)];                             \
        float4 b1 = *(const float4*)&Bs[k][(nbase) + 4];                         \
        unsigned long long bp0 = f2pack(b0.x, b0.y);                             \
        unsigned long long bp1 = f2pack(b0.z, b0.w);                             \
        unsigned long long bp2 = f2pack(b1.x, b1.y);                             \
        unsigned long long bp3 = f2pack(b1.z, b1.w);                             \
        float av[8] = {a0.x, a0.y, a0.z, a0.w, a1.x, a1.y, a1.z, a1.w};          \
        _Pragma("unroll")                                                        \
        for (int i = 0; i < 8; i++) {                                            \
            unsigned long long aa = f2pack(av[i], av[i]);                        \
            ffma2(acc[i][0], aa, bp0);                                           \
            ffma2(acc[i][1], aa, bp1);                                           \
            ffma2(acc[i][2], aa, bp2);                                           \
            ffma2(acc[i][3], aa, bp3);                                           \
        }                                                                        \
    }

// ---------------- transpose [R][C] -> [C][R], batched ----------------
__global__ void k_transpose(const float* __restrict__ in, float* __restrict__ out,
                            int R, int Ccols) {
    __shared__ float tile[32][33];
    int b = blockIdx.z;
    const float* ip = in + (size_t)b * R * Ccols;
    float* op = out + (size_t)b * R * Ccols;
    int c0 = blockIdx.x * 32, r0 = blockIdx.y * 32;
    #pragma unroll
    for (int i = threadIdx.y; i < 32; i += 8)
        tile[i][threadIdx.x] = ip[(size_t)(r0 + i) * Ccols + c0 + threadIdx.x];
    __syncthreads();
    #pragma unroll
    for (int i = threadIdx.y; i < 32; i += 8)
        op[(size_t)(c0 + i) * R + r0 + threadIdx.x] = tile[threadIdx.x][i];
}

// ---------------- GEMM 128x128 tile, 8x8 micro, f32x2 -------------------------
// out[b][m][n] = sum_k A[m][k]*Bm[b][n][k] + bias[m]; A [M][K], Bm [B][Nd][K]
__global__ __launch_bounds__(256) void k_gemm128(
        const float* __restrict__ A, const float* __restrict__ Bm,
        const float* __restrict__ bias, float* __restrict__ out,
        int M, int Nd, int K) {
    __shared__ float As[16][132];
    __shared__ float Bs[16][132];
    int tid = threadIdx.x;
    int tx = tid & 15, ty = tid >> 4;
    int m0 = blockIdx.y * 128, n0 = blockIdx.x * 128;
    const float* Ap = A + (size_t)m0 * K;
    const float* Bp = Bm + (size_t)blockIdx.z * Nd * K + (size_t)n0 * K;
    unsigned long long acc[8][4];
    #pragma unroll
    for (int i = 0; i < 8; i++)
        #pragma unroll
        for (int j = 0; j < 4; j++) acc[i][j] = 0ull;
    for (int k0 = 0; k0 < K; k0 += 16) {
        #pragma unroll
        for (int u = 0; u < 2; u++) {
            int f = tid + u * 256;
            int row = f >> 2, kq = (f & 3) << 2;
            float4 a = *(const float4*)(Ap + (size_t)row * K + k0 + kq);
            As[kq + 0][row] = a.x; As[kq + 1][row] = a.y;
            As[kq + 2][row] = a.z; As[kq + 3][row] = a.w;
            float4 b = *(const float4*)(Bp + (size_t)row * K + k0 + kq);
            Bs[kq + 0][row] = b.x; Bs[kq + 1][row] = b.y;
            Bs[kq + 2][row] = b.z; Bs[kq + 3][row] = b.w;
        }
        __syncthreads();
        #pragma unroll
        for (int k = 0; k < 16; k++) MICRO_8X8_STEP(As, Bs, ty * 8, tx * 8)
        __syncthreads();
    }
    #pragma unroll
    for (int i = 0; i < 8; i++) {
        int m = m0 + ty * 8 + i;
        float bv = bias[m];
        float o[8];
        f2unpack(acc[i][0], o[0], o[1]);
        f2unpack(acc[i][1], o[2], o[3]);
        f2unpack(acc[i][2], o[4], o[5]);
        f2unpack(acc[i][3], o[6], o[7]);
        float* dst = out + ((size_t)blockIdx.z * M + m) * Nd + n0 + tx * 8;
        float4 w0 = {o[0] + bv, o[1] + bv, o[2] + bv, o[3] + bv};
        float4 w1 = {o[4] + bv, o[5] + bv, o[6] + bv, o[7] + bv};
        *(float4*)dst = w0;
        *(float4*)(dst + 4) = w1;
    }
}

// ---------------- depthwise 5x5 conv + exact GELU ----------------
__global__ void k_dwconv(const float* __restrict__ xt, const float* __restrict__ w,
                         const float* __restrict__ b, float* __restrict__ out) {
    int n = blockIdx.x * 256 + threadIdx.x;
    int c = blockIdx.y, bb = blockIdx.z;
    int y = n >> 5, x = n & 31;
    const float* p = xt + ((size_t)bb * CC + c) * NN;
    const float* wf = w + c * 25;
    float acc = b[c];
    #pragma unroll
    for (int dy = 0; dy < 5; dy++) {
        int yy = y + dy - 2;
        if (yy < 0 || yy >= HH) continue;
        #pragma unroll
        for (int dx = 0; dx < 5; dx++) {
            int xx = x + dx - 2;
            if (xx < 0 || xx >= WW) continue;
            acc += p[yy * WW + xx] * wf[dy * 5 + dx];
        }
    }
    out[((size_t)bb * CC + c) * NN + n] = 0.5f * acc * (1.0f + erff(acc * 0.7071067811865476f));
}

// ---------------- offset head: 1x1 conv (16 out ch), tanh * 2 ----------------
__global__ void k_offproj(const float* __restrict__ h, const float* __restrict__ ow,
                          float* __restrict__ off) {
    int n = blockIdx.x * 256 + threadIdx.x;
    int oc = blockIdx.y, bb = blockIdx.z;
    const float* hp = h + (size_t)bb * CC * NN + n;
    const float* wp = ow + oc * CC;
    float acc = 0.f;
    for (int c = 0; c < CC; c++) acc += hp[(size_t)c * NN] * wp[c];
    off[((size_t)bb * 16 + oc) * NN + n] = tanhf(acc) * 2.0f;
}

// ---------------- sample coords (grid + offset, clip, -> pixel space) --------
__global__ void k_samp(const float* __restrict__ off, float* __restrict__ sxy) {
    int n = blockIdx.x * 256 + threadIdx.x;
    int hh = blockIdx.y, bb = blockIdx.z;
    float ox = off[((size_t)bb * 16 + hh * 2    ) * NN + n];
    float oy = off[((size_t)bb * 16 + hh * 2 + 1) * NN + n];
    int y = n >> 5, x = n & 31;
    float gx = -1.0f + 2.0f * x / 31.0f;
    float gy = -1.0f + 2.0f * y / 31.0f;
    float sx = fminf(fmaxf(gx + ox, -1.f), 1.f);
    float sy = fminf(fmaxf(gy + oy, -1.f), 1.f);
    size_t o = (((size_t)bb * NH + hh) * NN + n) * 2;
    sxy[o]     = (sx + 1.0f) * 16.0f - 0.5f;   // (s+1)*Wi/2 - 0.5
    sxy[o + 1] = (sy + 1.0f) * 16.0f - 0.5f;
}

// ---------------- bilinear grid sample (zeros padding) for K and V -----------
__global__ void k_gsample(const float* __restrict__ sxy, const float* __restrict__ Kg,
                          const float* __restrict__ Vg, float* __restrict__ Ks,
                          float* __restrict__ Vs) {
    int n = blockIdx.x * 256 + threadIdx.x;
    int d = blockIdx.y, bh = blockIdx.z;
    int bb = bh >> 3, hh = bh & 7;
    size_t so = ((size_t)bh * NN + n) * 2;
    float px = sxy[so], py = sxy[so + 1];
    float x0f = floorf(px), y0f = floorf(py);
    int x0 = (int)x0f, y0 = (int)y0f;
    float fx = px - x0f, fy = py - y0f;
    const float* kp = Kg + ((size_t)bb * CC + hh * HD + d) * NN;
    const float* vp = Vg + ((size_t)bb * CC + hh * HD + d) * NN;
    float ks = 0.f, vs = 0.f;
    #pragma unroll
    for (int dy = 0; dy < 2; dy++) {
        int yi = y0 + dy;
        if (yi < 0 || yi >= HH) continue;
        float wy = dy ? fy : 1.0f - fy;
        #pragma unroll
        for (int dx = 0; dx < 2; dx++) {
            int xi = x0 + dx;
            if (xi < 0 || xi >= WW) continue;
            float wt = wy * (dx ? fx : 1.0f - fx);
            int f = yi * WW + xi;
            ks += kp[f] * wt;
            vs += vp[f] * wt;
        }
    }
    size_t oo = ((size_t)bh * HD + d) * NN + n;
    Ks[oo] = ks;
    Vs[oo] = vs;
}

// ---------------- relative position bias table lookup (wsz=8) ----------------
__global__ void k_bias0(const float* __restrict__ table, float* __restrict__ b0) {
    int t = blockIdx.x * 256 + threadIdx.x;
    if (t >= 4096) return;
    int i = t >> 6, j = t & 63;
    int iy = i >> 3, ix = i & 7, jy = j >> 3, jx = j & 7;
    int idx = (iy - jy + 7) * 15 + (ix - jx + 7);
    b0[t] = table[idx];
}

// ---------------- bicubic resize matrix M [1024][64] and Mt ------------------
__global__ void k_bicubicM(float* __restrict__ M, float* __restrict__ Mt) {
    int r = blockIdx.x * 256 + threadIdx.x;
    if (r >= NN) return;
    for (int c = 0; c < 64; c++) { M[r * 64 + c] = 0.f; Mt[c * NN + r] = 0.f; }
    const float a = -0.75f;
    float src = (r + 0.5f) * (64.0f / 1024.0f) - 0.5f;
    float i0f = floorf(src);
    float t = src - i0f;
    int i0 = (int)i0f;
    #pragma unroll
    for (int k = -1; k <= 2; k++) {
        int idx = min(max(i0 + k, 0), 63);
        float d = fabsf(t - (float)k);
        float w;
        if (d <= 1.0f)      w = (a + 2.0f) * d * d * d - (a + 3.0f) * d * d + 1.0f;
        else if (d < 2.0f)  w = a * d * d * d - 5.0f * a * d * d + 8.0f * a * d - 4.0f * a;
        else                w = 0.0f;
        M[r * 64 + idx]  += w;
        Mt[idx * NN + r] += w;
    }
}

// tmp = M @ bias0  [1024][64]
__global__ void k_Mb0(const float* __restrict__ M, const float* __restrict__ b0,
                      float* __restrict__ tmp) {
    int t = blockIdx.x * 256 + threadIdx.x;    // 65536
    int r = t >> 6, j = t & 63;
    float acc = 0.f;
    for (int c = 0; c < 64; c++) acc += M[r * 64 + c] * b0[c * 64 + j];
    tmp[t] = acc;
}

// bias[i][j] = sum_e tmp[i][e] * Mt[e][j]
__global__ void k_biasfull(const float* __restrict__ tmp, const float* __restrict__ Mt,
                           float* __restrict__ bias) {
    int t = blockIdx.x * 256 + threadIdx.x;    // 1M
    int i = t >> 10, j = t & 1023;
    float acc = 0.f;
    for (int e = 0; e < 64; e++) acc += tmp[i * 64 + e] * Mt[e * NN + j];
    bias[t] = acc;
}

// ---------------- scores 128x128 tile, f32x2: S = 0.125*Q^T K + bias ---------
// Q stored [64 d][1024 i] (i contig), Ks [64 d][1024 j] (j contig)
__global__ __launch_bounds__(256) void k_scores2(
        const float* __restrict__ Qg, const float* __restrict__ Kg,
        const float* __restrict__ biasf, float* __restrict__ Sg) {
    __shared__ float As[16][132];
    __shared__ float Bs[16][132];
    int bh = blockIdx.z;
    int bb = bh >> 3, hh = bh & 7;
    const float* Qp = Qg + ((size_t)bb * CC + hh * HD) * NN;
    const float* Kp = Kg + (size_t)bh * HD * NN;
    int i0 = blockIdx.y * 128, j0 = blockIdx.x * 128;
    int tid = threadIdx.x, tx = tid & 15, ty = tid >> 4;
    unsigned long long acc[8][4];
    #pragma unroll
    for (int i = 0; i < 8; i++)
        #pragma unroll
        for (int j = 0; j < 4; j++) acc[i][j] = 0ull;
    for (int d0 = 0; d0 < HD; d0 += 16) {
        #pragma unroll
        for (int u = 0; u < 2; u++) {
            int f = tid + u * 256;
            int krow = f >> 5, iq = (f & 31) << 2;
            *(float4*)&As[krow][iq] = *(const float4*)(Qp + (size_t)(d0 + krow) * NN + i0 + iq);
            *(float4*)&Bs[krow][iq] = *(const float4*)(Kp + (size_t)(d0 + krow) * NN + j0 + iq);
        }
        __syncthreads();
        #pragma unroll
        for (int k = 0; k < 16; k++) MICRO_8X8_STEP(As, Bs, ty * 8, tx * 8)
        __syncthreads();
    }
    #pragma unroll
    for (int i = 0; i < 8; i++) {
        int ii = i0 + ty * 8 + i;
        float o[8];
        f2unpack(acc[i][0], o[0], o[1]);
        f2unpack(acc[i][1], o[2], o[3]);
        f2unpack(acc[i][2], o[4], o[5]);
        f2unpack(acc[i][3], o[6], o[7]);
        const float* bp = biasf + (size_t)ii * NN + j0 + tx * 8;
        float4 c0 = *(const float4*)bp;
        float4 c1 = *(const float4*)(bp + 4);
        float4 w0 = {o[0] * 0.125f + c0.x, o[1] * 0.125f + c0.y,
                     o[2] * 0.125f + c0.z, o[3] * 0.125f + c0.w};
        float4 w1 = {o[4] * 0.125f + c1.x, o[5] * 0.125f + c1.y,
                     o[6] * 0.125f + c1.z, o[7] * 0.125f + c1.w};
        float* dst = Sg + ((size_t)bh << 20) + (size_t)ii * NN + j0 + tx * 8;
        *(float4*)dst = w0;
        *(float4*)(dst + 4) = w1;
    }
}

// ---------------- softmax over rows of 1024 (in place) -----------------------
__global__ void k_softmax(float* __restrict__ S) {
    float* p = S + (size_t)blockIdx.x * NN;
    int t = threadIdx.x;
    float v0 = p[t], v1 = p[t + 256], v2 = p[t + 512], v3 = p[t + 768];
    float m = fmaxf(fmaxf(v0, v1), fmaxf(v2, v3));
    __shared__ float rmax[8], rsum[8], bc[2];
    #pragma unroll
    for (int o = 16; o > 0; o >>= 1) m = fmaxf(m, __shfl_xor_sync(0xffffffffu, m, o));
    if ((t & 31) == 0) rmax[t >> 5] = m;
    __syncthreads();
    if (t == 0) {
        float mm = rmax[0];
        #pragma unroll
        for (int i = 1; i < 8; i++) mm = fmaxf(mm, rmax[i]);
        bc[0] = mm;
    }
    __syncthreads();
    m = bc[0];
    v0 = expf(v0 - m); v1 = expf(v1 - m); v2 = expf(v2 - m); v3 = expf(v3 - m);
    float s = v0 + v1 + v2 + v3;
    #pragma unroll
    for (int o = 16; o > 0; o >>= 1) s += __shfl_xor_sync(0xffffffffu, s, o);
    if ((t & 31) == 0) rsum[t >> 5] = s;
    __syncthreads();
    if (t == 0) {
        float ss = 0.f;
        #pragma unroll
        for (int i = 0; i < 8; i++) ss += rsum[i];
        bc[1] = ss;
    }
    __syncthreads();
    float inv = 1.0f / bc[1];
    p[t] = v0 * inv; p[t + 256] = v1 * inv; p[t + 512] = v2 * inv; p[t + 768] = v3 * inv;
}

// ---------------- attout 128x64 tile, f32x2: out = P @ V^T -> att [B][N][C] --
__global__ __launch_bounds__(128) void k_attout2(
        const float* __restrict__ Pg, const float* __restrict__ Vsg,
        float* __restrict__ att) {
    __shared__ float As[16][132];
    __shared__ float Bs[16][68];
    int bh = blockIdx.z;
    int bb = bh >> 3, hh = bh & 7;
    const float* Pp = Pg + ((size_t)bh << 20);     // [1024 i][1024 j]
    const float* Vp = Vsg + (size_t)bh * HD * NN;  // [64 d][1024 j]
    int i0 = blockIdx.y * 128;
    int tid = threadIdx.x, tx = tid & 7, ty = tid >> 3;   // tx->d, ty->i
    unsigned long long acc[8][4];
    #pragma unroll
    for (int i = 0; i < 8; i++)
        #pragma unroll
        for (int j = 0; j < 4; j++) acc[i][j] = 0ull;
    for (int k0 = 0; k0 < NN; k0 += 16) {
        #pragma unroll
        for (int u = 0; u < 4; u++) {
            int f = tid + u * 128;
            int row = f >> 2, kq = (f & 3) << 2;
            float4 a = *(const float4*)(Pp + (size_t)(i0 + row) * NN + k0 + kq);
            As[kq + 0][row] = a.x; As[kq + 1][row] = a.y;
            As[kq + 2][row] = a.z; As[kq + 3][row] = a.w;
        }
        #pragma unroll
        for (int u = 0; u < 2; u++) {
            int f = tid + u * 128;
            int row = f >> 2, kq = (f & 3) << 2;
            float4 b = *(const float4*)(Vp + (size_t)row * NN + k0 + kq);
            Bs[kq + 0][row] = b.x; Bs[kq + 1][row] = b.y;
            Bs[kq + 2][row] = b.z; Bs[kq + 3][row] = b.w;
        }
        __syncthreads();
        #pragma unroll
        for (int k = 0; k < 16; k++) MICRO_8X8_STEP(As, Bs, ty * 8, tx * 8)
        __syncthreads();
    }
    #pragma unroll
    for (int i = 0; i < 8; i++) {
        int ii = i0 + ty * 8 + i;
        float o[8];
        f2unpack(acc[i][0], o[0], o[1]);
        f2unpack(acc[i][1], o[2], o[3]);
        f2unpack(acc[i][2], o[4], o[5]);
        f2unpack(acc[i][3], o[6], o[7]);
        float* dst = att + ((size_t)bb * NN + ii) * CC + hh * HD + tx * 8;
        float4 w0 = {o[0], o[1], o[2], o[3]};
        float4 w1 = {o[4], o[5], o[6], o[7]};
        *(float4*)dst = w0;
        *(float4*)(dst + 4) = w1;
    }
}

// ---------------- launch ----------------
extern "C" void kernel_launch(void* const* d_in, const int* in_sizes, int n_in,
                              void* d_out, int out_size) {
    const float* x     = (const float*)d_in[0];
    const float* q_w   = (const float*)d_in[1];
    const float* q_b   = (const float*)d_in[2];
    const float* k_w   = (const float*)d_in[3];
    const float* k_b   = (const float*)d_in[4];
    const float* v_w   = (const float*)d_in[5];
    const float* v_b   = (const float*)d_in[6];
    const float* o_w   = (const float*)d_in[7];
    const float* o_b   = (const float*)d_in[8];
    const float* dw_w  = (const float*)d_in[9];
    const float* dw_b  = (const float*)d_in[10];
    const float* off_w = (const float*)d_in[11];
    const float* table = (const float*)d_in[12];

    float *p_xt, *p_q, *p_k, *p_v, *p_h, *p_off, *p_sxy, *p_ks, *p_vs;
    float *p_b0, *p_M, *p_Mt, *p_tmp, *p_bias, *p_sc, *p_att, *p_oo;
    cudaGetSymbolAddress((void**)&p_xt,  g_xt);
    cudaGetSymbolAddress((void**)&p_q,   g_q);
    cudaGetSymbolAddress((void**)&p_k,   g_k);
    cudaGetSymbolAddress((void**)&p_v,   g_v);
    cudaGetSymbolAddress((void**)&p_h,   g_h);
    cudaGetSymbolAddress((void**)&p_off, g_off);
    cudaGetSymbolAddress((void**)&p_sxy, g_sxy);
    cudaGetSymbolAddress((void**)&p_ks,  g_ksmp);
    cudaGetSymbolAddress((void**)&p_vs,  g_vsmp);
    cudaGetSymbolAddress((void**)&p_b0,  g_b0);
    cudaGetSymbolAddress((void**)&p_M,   g_M);
    cudaGetSymbolAddress((void**)&p_Mt,  g_Mt);
    cudaGetSymbolAddress((void**)&p_tmp, g_tmpMB);
    cudaGetSymbolAddress((void**)&p_bias,g_bias);
    cudaGetSymbolAddress((void**)&p_sc,  g_sc);
    cudaGetSymbolAddress((void**)&p_att, g_att);
    cudaGetSymbolAddress((void**)&p_oo,  g_oo);

    // x [B][N][C] -> xt [B][C][N] (for spatially-coalesced dwconv reads)
    k_transpose<<<dim3(CC / 32, NN / 32, BB), dim3(32, 8)>>>(x, p_xt, NN, CC);

    // Q/K/V projections (x itself is k-contiguous [B][N][C])
    k_gemm128<<<dim3(8, 4, BB), 256>>>(q_w, x, q_b, p_q, CC, NN, CC);
    k_gemm128<<<dim3(8, 4, BB), 256>>>(k_w, x, k_b, p_k, CC, NN, CC);
    k_gemm128<<<dim3(8, 4, BB), 256>>>(v_w, x, v_b, p_v, CC, NN, CC);

    // offset network
    k_dwconv <<<dim3(4, CC, BB), 256>>>(p_xt, dw_w, dw_b, p_h);
    k_offproj<<<dim3(4, 16, BB), 256>>>(p_h, off_w, p_off);
    k_samp   <<<dim3(4, NH, BB), 256>>>(p_off, p_sxy);

    // deformable sampling of K and V
    k_gsample<<<dim3(4, HD, BB * NH), 256>>>(p_sxy, p_k, p_v, p_ks, p_vs);

    // relative-position bias: table -> 64x64 -> bicubic resize to 1024x1024
    k_bias0   <<<16, 256>>>(table, p_b0);
    k_bicubicM<<<4, 256>>>(p_M, p_Mt);
    k_Mb0     <<<256, 256>>>(p_M, p_b0, p_tmp);
    k_biasfull<<<4096, 256>>>(p_tmp, p_Mt, p_bias);

    // attention
    k_scores2<<<dim3(8, 8, BB * NH), 256>>>(p_q, p_ks, p_bias, p_sc);
    k_softmax<<<BB * NH * NN, 256>>>(p_sc);
    k_attout2<<<dim3(1, 8, BB * NH), 128>>>(p_sc, p_vs, p_att);

    // output projection + final transpose to [B][N][C]
    k_gemm128  <<<dim3(8, 4, BB), 256>>>(o_w, p_att, o_b, p_oo, CC, NN, CC);
    k_transpose<<<dim3(NN / 32, CC / 32, BB), dim3(32, 8)>>>(p_oo, (float*)d_out, CC, NN);
}